// round 3
// baseline (speedup 1.0000x reference)
#include <cuda_runtime.h>
#include <cuda_bf16.h>

#define NN     5000   // nodes
#define TIN    12     // input timesteps
#define TTOT   24     // output timesteps
#define BB     16     // batch
#define CC     4      // channels
#define KNB    16     // neighbors
#define NH     4      // heads
#define DIN    48     // T*H
#define DOUT   12     // extrapolated steps

// Transposed x scratch: xt[n][b][c][t]  (t fastest; 768 floats / 3KB per node)
__device__ float g_xt[(size_t)NN * BB * CC * TIN];

typedef unsigned long long ull;

__device__ __forceinline__ ull pk2(float lo, float hi) {
    ull r;
    asm("mov.b64 %0, {%1, %2};" : "=l"(r) : "f"(lo), "f"(hi));
    return r;
}
__device__ __forceinline__ void upk2(float& lo, float& hi, ull v) {
    asm("mov.b64 {%0, %1}, %2;" : "=f"(lo), "=f"(hi) : "l"(v));
}
__device__ __forceinline__ void fma2(ull& d, ull a, ull b, ull c) {
    asm("fma.rn.f32x2 %0, %1, %2, %3;" : "=l"(d) : "l"(a), "l"(b), "l"(c));
}

// ---------------------------------------------------------------------------
// Kernel A (fused): read x (B,T,N,C) once;
//   (1) copy into out[:, 0:12] (coalesced),
//   (2) transpose into g_xt[n][b][c][t] via smem tile (coalesced writes).
// ---------------------------------------------------------------------------
#define NT 8
#define SROW 772   // 768 floats per node + 4 pad

__global__ __launch_bounds__(256) void k_prep(const float* __restrict__ x,
                                              float* __restrict__ out) {
    __shared__ __align__(16) float s[NT][SROW];

    const int tid = threadIdx.x;
    const int n0  = blockIdx.x * NT;
    const int nn  = tid & (NT - 1);
    const int mb  = tid >> 3;            // 0..31
    const int n   = n0 + nn;
    const bool valid = (n < NN);

    const float4* __restrict__ x4 = (const float4*)x;
    float4* __restrict__ out4 = (float4*)out;

    #pragma unroll
    for (int i = 0; i < 6; i++) {
        int m = mb + (i << 5);           // 0..191, m = b*12 + t
        if (valid) {
            float4 v = x4[(size_t)m * NN + n];
            int b = m / TIN, t = m % TIN;
            out4[((size_t)b * TTOT + t) * NN + n] = v;   // copy half of output
            float* sp = &s[nn][b * 48 + t];              // [b][c][t] layout
            sp[0]  = v.x;
            sp[12] = v.y;
            sp[24] = v.z;
            sp[36] = v.w;
        }
    }
    __syncthreads();

    float4* __restrict__ xt4 = (float4*)g_xt;
    #pragma unroll
    for (int i = 0; i < 6; i++) {
        int g   = tid + (i << 8);        // 0..1535
        int nn2 = g / 192;
        int w   = g - nn2 * 192;
        int n2  = n0 + nn2;
        if (n2 < NN) {
            float4 v = *(const float4*)&s[nn2][w << 2];
            xt4[(size_t)n2 * 192 + w] = v;
        }
    }
}

// ---------------------------------------------------------------------------
// Kernel B: block per node, 192 threads. Thread tid owns node-row chunk tid
// (16B = 4 timesteps): tid = b*12 + c*3 + tc  (tc = t-chunk, t in [4tc,4tc+4)).
// Gather: per k ONE dense LDG.128 per thread (warp = 512B contiguous),
// 2-deep software pipeline. acc[2 tpair][4 head] in f32x2.
// Linear partials per thread, 3-way t-chunk reduction in smem, ReLU, store.
// ---------------------------------------------------------------------------
__global__ __launch_bounds__(192) void k_main(
    const float* __restrict__ dists,
    const float* __restrict__ W,
    const float* __restrict__ bias,
    const int*   __restrict__ neighbors,
    float* __restrict__ out)
{
    __shared__ ull   swp[KNB][NH];                // packed (w,w) per (k,h)
    __shared__ int   snb[KNB];
    __shared__ __align__(16) float sW[DIN * DOUT];
    __shared__ float sb[DOUT];
    __shared__ float sred[2][64][DOUT];           // partials from tc=1,2

    const int n   = blockIdx.x;
    const int tid = threadIdx.x;

    if (tid < KNB) {
        float d  = dists[n * KNB + tid];
        float e  = __expf(-d * d * (1.0f / 144.0f));   // sigma^2 = 36, H = 4
        float e2 = e * e;
        swp[tid][0] = pk2(e, e);
        swp[tid][1] = pk2(e2, e2);
        swp[tid][2] = pk2(e2 * e, e2 * e);
        swp[tid][3] = pk2(e2 * e2, e2 * e2);
        snb[tid]    = neighbors[n * KNB + tid];
    }
    #pragma unroll
    for (int i = tid; i < DIN * DOUT; i += 192) sW[i] = W[i];
    if (tid < DOUT) sb[tid] = bias[tid];
    __syncthreads();

    const int b  = tid / 12;
    const int r  = tid - b * 12;
    const int c  = r >> 2 == 0 ? r / 3 : r / 3;   // c = r/3
    const int tc = r - (r / 3) * 3;               // tc = r%3
    const int cc = r / 3;

    union F4U { float4 f; ull u[2]; };

    ull acc[2][NH];
    #pragma unroll
    for (int tp = 0; tp < 2; tp++)
        #pragma unroll
        for (int h = 0; h < NH; h++) acc[tp][h] = 0ull;

    // Gather + aggregate, 2-deep pipeline. Chunk address = node*192 + tid.
    const float4* __restrict__ xp = ((const float4*)g_xt) + tid;
    F4U v0, v1, vn;
    v0.f = xp[(size_t)snb[0] * 192];
    v1.f = xp[(size_t)snb[1] * 192];

    #pragma unroll
    for (int k = 0; k < KNB; k++) {
        if (k + 2 < KNB) vn.f = xp[(size_t)snb[k + 2] * 192];
        ull x0 = v0.u[0], x1 = v0.u[1];
        #pragma unroll
        for (int h = 0; h < NH; h++) {
            ull w = swp[k][h];
            fma2(acc[0][h], x0, w, acc[0][h]);
            fma2(acc[1][h], x1, w, acc[1][h]);
        }
        v0 = v1;
        v1 = vn;
    }

    // Linear partial: y[o] += acc[t][h] * W[(t*4+h)][o] over this thread's 4 t's
    ull y2[6];
    if (tc == 0) {
        #pragma unroll
        for (int op = 0; op < 6; op++) y2[op] = pk2(sb[2 * op], sb[2 * op + 1]);
    } else {
        #pragma unroll
        for (int op = 0; op < 6; op++) y2[op] = 0ull;
    }

    #pragma unroll
    for (int tp = 0; tp < 2; tp++) {
        const int t0 = 4 * tc + 2 * tp;           // global t of pair
        #pragma unroll
        for (int h = 0; h < NH; h++) {
            float a0, a1;
            upk2(a0, a1, acc[tp][h]);
            ull s0 = pk2(a0, a0);
            ull s1 = pk2(a1, a1);
            const ull* __restrict__ w0 = (const ull*)&sW[((t0)     * NH + h) * DOUT];
            const ull* __restrict__ w1 = (const ull*)&sW[((t0 + 1) * NH + h) * DOUT];
            #pragma unroll
            for (int op = 0; op < 6; op++) {
                fma2(y2[op], s0, w0[op], y2[op]);
                fma2(y2[op], s1, w1[op], y2[op]);
            }
        }
    }

    // Reduce the 3 t-chunk partials per (b,c)
    const int bc = b * CC + cc;
    if (tc > 0) {
        #pragma unroll
        for (int op = 0; op < 6; op++) {
            float y0, y1;
            upk2(y0, y1, y2[op]);
            sred[tc - 1][bc][2 * op]     = y0;
            sred[tc - 1][bc][2 * op + 1] = y1;
        }
    }
    __syncthreads();

    if (tc == 0) {
        float* __restrict__ op_ =
            out + (((size_t)b * TTOT + TIN) * NN + n) * CC + cc;
        #pragma unroll
        for (int op = 0; op < 6; op++) {
            float y0, y1;
            upk2(y0, y1, y2[op]);
            y0 += sred[0][bc][2 * op]     + sred[1][bc][2 * op];
            y1 += sred[0][bc][2 * op + 1] + sred[1][bc][2 * op + 1];
            op_[(size_t)(2 * op)     * NN * CC] = fmaxf(y0, 0.0f);
            op_[(size_t)(2 * op + 1) * NN * CC] = fmaxf(y1, 0.0f);
        }
    }
}

// ---------------------------------------------------------------------------
extern "C" void kernel_launch(void* const* d_in, const int* in_sizes, int n_in,
                              void* d_out, int out_size)
{
    const float* x         = (const float*)d_in[0];
    const float* dists     = (const float*)d_in[1];
    const float* W         = (const float*)d_in[2];
    const float* bias      = (const float*)d_in[3];
    const int*   neighbors = (const int*)  d_in[4];
    float* out = (float*)d_out;

    k_prep<<<(NN + NT - 1) / NT, 256>>>(x, out);
    k_main<<<NN, 192>>>(dists, W, bias, neighbors, out);
}

// round 6
// speedup vs baseline: 2.8062x; 2.8062x over previous
#include <cuda_runtime.h>
#include <cuda_bf16.h>

#define NN     5000   // nodes
#define TIN    12     // input timesteps
#define TTOT   24     // output timesteps
#define BB     16     // batch
#define CC     4      // channels
#define KNB    16     // neighbors
#define NH     4      // heads
#define DIN    48     // T*H
#define DOUT   12     // extrapolated steps

// Transposed x scratch: xt[n][b][c][t]  (t fastest; 768 floats / 3KB per node;
// as float4 chunks: m = b*12 + c*3 + tq, chunk holds t = 4*tq .. 4*tq+3)
__device__ float g_xt[(size_t)NN * BB * CC * TIN];

typedef unsigned long long ull;

__device__ __forceinline__ ull pk2(float lo, float hi) {
    ull r;
    asm("mov.b64 %0, {%1, %2};" : "=l"(r) : "f"(lo), "f"(hi));
    return r;
}
__device__ __forceinline__ void upk2(float& lo, float& hi, ull v) {
    asm("mov.b64 {%0, %1}, %2;" : "=f"(lo), "=f"(hi) : "l"(v));
}
__device__ __forceinline__ void fma2(ull& d, ull a, ull b, ull c) {
    asm("fma.rn.f32x2 %0, %1, %2, %3;" : "=l"(d) : "l"(a), "l"(b), "l"(c));
}

// ---------------------------------------------------------------------------
// Kernel A (fused): read x (B,T,N,C) once;
//   (1) copy into out[:, 0:12] (coalesced),
//   (2) transpose into g_xt[n][b][c][t] via smem tile (coalesced writes).
// ---------------------------------------------------------------------------
#define NT 8
#define SROW 772   // 768 floats per node + 4 pad

__global__ __launch_bounds__(256) void k_prep(const float* __restrict__ x,
                                              float* __restrict__ out) {
    __shared__ __align__(16) float s[NT][SROW];

    const int tid = threadIdx.x;
    const int n0  = blockIdx.x * NT;
    const int nn  = tid & (NT - 1);
    const int mb  = tid >> 3;            // 0..31
    const int n   = n0 + nn;
    const bool valid = (n < NN);

    const float4* __restrict__ x4 = (const float4*)x;
    float4* __restrict__ out4 = (float4*)out;

    #pragma unroll
    for (int i = 0; i < 6; i++) {
        int m = mb + (i << 5);           // 0..191, m = b*12 + t
        if (valid) {
            float4 v = x4[(size_t)m * NN + n];
            int b = m / TIN, t = m % TIN;
            out4[((size_t)b * TTOT + t) * NN + n] = v;   // copy half of output
            float* sp = &s[nn][b * 48 + t];              // [b][c][t] layout
            sp[0]  = v.x;
            sp[12] = v.y;
            sp[24] = v.z;
            sp[36] = v.w;
        }
    }
    __syncthreads();

    float4* __restrict__ xt4 = (float4*)g_xt;
    #pragma unroll
    for (int i = 0; i < 6; i++) {
        int g   = tid + (i << 8);        // 0..1535
        int nn2 = g / 192;
        int w   = g - nn2 * 192;
        int n2  = n0 + nn2;
        if (n2 < NN) {
            float4 v = *(const float4*)&s[nn2][w << 2];
            xt4[(size_t)n2 * 192 + w] = v;
        }
    }
}

// ---------------------------------------------------------------------------
// Kernel B: block per node, 96 threads.
// Phase A (gather/aggregate): thread owns float4 chunks {tid, tid+96} of the
//   768-float node row -> every LDG.128 is 512B-contiguous per warp (4 wf).
//   Weights are elementwise-uniform, so chunk ownership is free to choose.
//   acc[2 chunk][2 half][4 head] in f32x2. 2-deep software pipeline.
// Stage via smem sagg[h][m] (conflict-free), then
// Phase B (linear): threads 0..63 = (b,c) read their own 3 chunks per head,
//   48x12 linear with warp-uniform (broadcast) sW reads, ReLU, store.
// ---------------------------------------------------------------------------
__global__ __launch_bounds__(96, 10) void k_main(
    const float* __restrict__ dists,
    const float* __restrict__ W,
    const float* __restrict__ bias,
    const int*   __restrict__ neighbors,
    float* __restrict__ out)
{
    __shared__ ull   swp[KNB][NH];                 // packed (w,w) per (k,h)
    __shared__ int   snb[KNB];
    __shared__ __align__(16) float sW[DIN * DOUT];
    __shared__ float sb[DOUT];
    __shared__ __align__(16) float sagg[NH][192 * 4];   // [h][m] as float4

    const int n   = blockIdx.x;
    const int tid = threadIdx.x;

    if (tid < KNB) {
        float d  = dists[n * KNB + tid];
        float e  = __expf(-d * d * (1.0f / 144.0f));   // sigma^2 = 36, H = 4
        float e2 = e * e;
        swp[tid][0] = pk2(e, e);
        swp[tid][1] = pk2(e2, e2);
        swp[tid][2] = pk2(e2 * e, e2 * e);
        swp[tid][3] = pk2(e2 * e2, e2 * e2);
        snb[tid]    = neighbors[n * KNB + tid];
    }
    #pragma unroll
    for (int i = tid; i < DIN * DOUT; i += 96) sW[i] = W[i];
    if (tid < DOUT) sb[tid] = bias[tid];
    __syncthreads();

    union F4U { float4 f; ull u[2]; };

    ull acc[2][2][NH];
    #pragma unroll
    for (int ch = 0; ch < 2; ch++)
        #pragma unroll
        for (int u = 0; u < 2; u++)
            #pragma unroll
            for (int h = 0; h < NH; h++) acc[ch][u][h] = 0ull;

    const float4* __restrict__ xp = ((const float4*)g_xt) + tid;

    F4U c0, c1, p0, p1;
    {
        size_t base = (size_t)snb[0] * 192;
        c0.f = xp[base];
        c1.f = xp[base + 96];
    }
    #pragma unroll
    for (int k = 0; k < KNB; k++) {
        if (k + 1 < KNB) {
            size_t base = (size_t)snb[k + 1] * 192;
            p0.f = xp[base];
            p1.f = xp[base + 96];
        }
        #pragma unroll
        for (int h = 0; h < NH; h++) {
            ull w = swp[k][h];
            fma2(acc[0][0][h], c0.u[0], w, acc[0][0][h]);
            fma2(acc[0][1][h], c0.u[1], w, acc[0][1][h]);
            fma2(acc[1][0][h], c1.u[0], w, acc[1][0][h]);
            fma2(acc[1][1][h], c1.u[1], w, acc[1][1][h]);
        }
        c0 = p0;
        c1 = p1;
    }

    // Stage aggregated chunks: sagg[h][m], fully coalesced STS.128
    float4* __restrict__ sagg4 = (float4*)sagg;
    #pragma unroll
    for (int h = 0; h < NH; h++) {
        F4U o0, o1;
        o0.u[0] = acc[0][0][h]; o0.u[1] = acc[0][1][h];
        o1.u[0] = acc[1][0][h]; o1.u[1] = acc[1][1][h];
        sagg4[h * 192 + tid]      = o0.f;
        sagg4[h * 192 + tid + 96] = o1.f;
    }
    __syncthreads();

    if (tid < 64) {
        // (b,c) = tid; its chunks are m = 3*tid + tq
        ull y2[6];
        #pragma unroll
        for (int op = 0; op < 6; op++) y2[op] = pk2(sb[2 * op], sb[2 * op + 1]);

        #pragma unroll
        for (int tq = 0; tq < 3; tq++) {
            #pragma unroll
            for (int h = 0; h < NH; h++) {
                F4U f;
                f.f = sagg4[h * 192 + 3 * tid + tq];
                float fe[4] = { f.f.x, f.f.y, f.f.z, f.f.w };
                #pragma unroll
                for (int e = 0; e < 4; e++) {
                    int t = 4 * tq + e;
                    ull s = pk2(fe[e], fe[e]);
                    const ull* __restrict__ wr =
                        (const ull*)&sW[(t * NH + h) * DOUT];
                    #pragma unroll
                    for (int op = 0; op < 6; op++)
                        fma2(y2[op], s, wr[op], y2[op]);
                }
            }
        }

        const int b = tid >> 2;
        const int c = tid & 3;
        float* __restrict__ op_ =
            out + (((size_t)b * TTOT + TIN) * NN + n) * CC + c;
        #pragma unroll
        for (int op = 0; op < 6; op++) {
            float y0, y1;
            upk2(y0, y1, y2[op]);
            op_[(size_t)(2 * op)     * NN * CC] = fmaxf(y0, 0.0f);
            op_[(size_t)(2 * op + 1) * NN * CC] = fmaxf(y1, 0.0f);
        }
    }
}

// ---------------------------------------------------------------------------
extern "C" void kernel_launch(void* const* d_in, const int* in_sizes, int n_in,
                              void* d_out, int out_size)
{
    const float* x         = (const float*)d_in[0];
    const float* dists     = (const float*)d_in[1];
    const float* W         = (const float*)d_in[2];
    const float* bias      = (const float*)d_in[3];
    const int*   neighbors = (const int*)  d_in[4];
    float* out = (float*)d_out;

    k_prep<<<(NN + NT - 1) / NT, 256>>>(x, out);
    k_main<<<NN, 96>>>(dists, W, bias, neighbors, out);
}

// round 7
// speedup vs baseline: 2.8462x; 1.0143x over previous
#include <cuda_runtime.h>
#include <cuda_bf16.h>

#define NN     5000   // nodes
#define TIN    12     // input timesteps
#define TTOT   24     // output timesteps
#define BB     16     // batch
#define CC     4      // channels
#define KNB    16     // neighbors
#define NH     4      // heads
#define DIN    48     // T*H
#define DOUT   12     // extrapolated steps

// Transposed x scratch: xt[n][b][c][t]  (t fastest; 768 floats / 3KB per node;
// as float4 chunks: m = b*12 + c*3 + tq, chunk holds t = 4*tq .. 4*tq+3)
__device__ float g_xt[(size_t)NN * BB * CC * TIN];

typedef unsigned long long ull;

__device__ __forceinline__ ull pk2(float lo, float hi) {
    ull r;
    asm("mov.b64 %0, {%1, %2};" : "=l"(r) : "f"(lo), "f"(hi));
    return r;
}
__device__ __forceinline__ void upk2(float& lo, float& hi, ull v) {
    asm("mov.b64 {%0, %1}, %2;" : "=f"(lo), "=f"(hi) : "l"(v));
}
__device__ __forceinline__ void fma2(ull& d, ull a, ull b, ull c) {
    asm("fma.rn.f32x2 %0, %1, %2, %3;" : "=l"(d) : "l"(a), "l"(b), "l"(c));
}

// ---------------------------------------------------------------------------
// Kernel A (fused): read x (B,T,N,C) once;
//   (1) copy into out[:, 0:12] (coalesced),
//   (2) transpose into g_xt[n][b][c][t] via smem tile (coalesced writes).
// ---------------------------------------------------------------------------
#define NT 8
#define SROW 772   // 768 floats per node + 4 pad

__global__ __launch_bounds__(256) void k_prep(const float* __restrict__ x,
                                              float* __restrict__ out) {
    __shared__ __align__(16) float s[NT][SROW];

    const int tid = threadIdx.x;
    const int n0  = blockIdx.x * NT;
    const int nn  = tid & (NT - 1);
    const int mb  = tid >> 3;            // 0..31
    const int n   = n0 + nn;
    const bool valid = (n < NN);

    const float4* __restrict__ x4 = (const float4*)x;
    float4* __restrict__ out4 = (float4*)out;

    #pragma unroll
    for (int i = 0; i < 6; i++) {
        int m = mb + (i << 5);           // 0..191, m = b*12 + t
        if (valid) {
            float4 v = x4[(size_t)m * NN + n];
            int b = m / TIN, t = m % TIN;
            out4[((size_t)b * TTOT + t) * NN + n] = v;   // copy half of output
            float* sp = &s[nn][b * 48 + t];              // [b][c][t] layout
            sp[0]  = v.x;
            sp[12] = v.y;
            sp[24] = v.z;
            sp[36] = v.w;
        }
    }
    __syncthreads();

    float4* __restrict__ xt4 = (float4*)g_xt;
    #pragma unroll
    for (int i = 0; i < 6; i++) {
        int g   = tid + (i << 8);        // 0..1535
        int nn2 = g / 192;
        int w   = g - nn2 * 192;
        int n2  = n0 + nn2;
        if (n2 < NN) {
            float4 v = *(const float4*)&s[nn2][w << 2];
            xt4[(size_t)n2 * 192 + w] = v;
        }
    }
}

// ---------------------------------------------------------------------------
// Kernel B: block per node, 96 threads.
// Phase A (gather/aggregate): thread owns float4 chunks {tid, tid+96} of the
//   768-float node row -> every LDG.128 is 512B-contiguous per warp (4 wf).
//   Weights are elementwise-uniform, so chunk ownership is free to choose.
//   acc[2 chunk][2 half][4 head] in f32x2. 2-deep software pipeline.
// Stage via smem sagg[h][m] (conflict-free), then
// Phase B (linear): threads 0..63 = (b,c) read their own 3 chunks per head,
//   48x12 linear with warp-uniform (broadcast) sW reads, ReLU, store.
// ---------------------------------------------------------------------------
__global__ __launch_bounds__(96, 10) void k_main(
    const float* __restrict__ dists,
    const float* __restrict__ W,
    const float* __restrict__ bias,
    const int*   __restrict__ neighbors,
    float* __restrict__ out)
{
    __shared__ ull   swp[KNB][NH];                 // packed (w,w) per (k,h)
    __shared__ int   snb[KNB];
    __shared__ __align__(16) float sW[DIN * DOUT];
    __shared__ float sb[DOUT];
    __shared__ __align__(16) float sagg[NH][192 * 4];   // [h][m] as float4

    const int n   = blockIdx.x;
    const int tid = threadIdx.x;

    if (tid < KNB) {
        float d  = dists[n * KNB + tid];
        float e  = __expf(-d * d * (1.0f / 144.0f));   // sigma^2 = 36, H = 4
        float e2 = e * e;
        swp[tid][0] = pk2(e, e);
        swp[tid][1] = pk2(e2, e2);
        swp[tid][2] = pk2(e2 * e, e2 * e);
        swp[tid][3] = pk2(e2 * e2, e2 * e2);
        snb[tid]    = neighbors[n * KNB + tid];
    }
    #pragma unroll
    for (int i = tid; i < DIN * DOUT; i += 96) sW[i] = W[i];
    if (tid < DOUT) sb[tid] = bias[tid];
    __syncthreads();

    union F4U { float4 f; ull u[2]; };

    ull acc[2][2][NH];
    #pragma unroll
    for (int ch = 0; ch < 2; ch++)
        #pragma unroll
        for (int u = 0; u < 2; u++)
            #pragma unroll
            for (int h = 0; h < NH; h++) acc[ch][u][h] = 0ull;

    const float4* __restrict__ xp = ((const float4*)g_xt) + tid;

    F4U c0, c1, p0, p1;
    {
        size_t base = (size_t)snb[0] * 192;
        c0.f = xp[base];
        c1.f = xp[base + 96];
    }
    #pragma unroll
    for (int k = 0; k < KNB; k++) {
        if (k + 1 < KNB) {
            size_t base = (size_t)snb[k + 1] * 192;
            p0.f = xp[base];
            p1.f = xp[base + 96];
        }
        #pragma unroll
        for (int h = 0; h < NH; h++) {
            ull w = swp[k][h];
            fma2(acc[0][0][h], c0.u[0], w, acc[0][0][h]);
            fma2(acc[0][1][h], c0.u[1], w, acc[0][1][h]);
            fma2(acc[1][0][h], c1.u[0], w, acc[1][0][h]);
            fma2(acc[1][1][h], c1.u[1], w, acc[1][1][h]);
        }
        c0 = p0;
        c1 = p1;
    }

    // Stage aggregated chunks: sagg[h][m], fully coalesced STS.128
    float4* __restrict__ sagg4 = (float4*)sagg;
    #pragma unroll
    for (int h = 0; h < NH; h++) {
        F4U o0, o1;
        o0.u[0] = acc[0][0][h]; o0.u[1] = acc[0][1][h];
        o1.u[0] = acc[1][0][h]; o1.u[1] = acc[1][1][h];
        sagg4[h * 192 + tid]      = o0.f;
        sagg4[h * 192 + tid + 96] = o1.f;
    }
    __syncthreads();

    if (tid < 64) {
        // (b,c) = tid; its chunks are m = 3*tid + tq
        ull y2[6];
        #pragma unroll
        for (int op = 0; op < 6; op++) y2[op] = pk2(sb[2 * op], sb[2 * op + 1]);

        #pragma unroll
        for (int tq = 0; tq < 3; tq++) {
            #pragma unroll
            for (int h = 0; h < NH; h++) {
                F4U f;
                f.f = sagg4[h * 192 + 3 * tid + tq];
                float fe[4] = { f.f.x, f.f.y, f.f.z, f.f.w };
                #pragma unroll
                for (int e = 0; e < 4; e++) {
                    int t = 4 * tq + e;
                    ull s = pk2(fe[e], fe[e]);
                    const ull* __restrict__ wr =
                        (const ull*)&sW[(t * NH + h) * DOUT];
                    #pragma unroll
                    for (int op = 0; op < 6; op++)
                        fma2(y2[op], s, wr[op], y2[op]);
                }
            }
        }

        const int b = tid >> 2;
        const int c = tid & 3;
        float* __restrict__ op_ =
            out + (((size_t)b * TTOT + TIN) * NN + n) * CC + c;
        #pragma unroll
        for (int op = 0; op < 6; op++) {
            float y0, y1;
            upk2(y0, y1, y2[op]);
            op_[(size_t)(2 * op)     * NN * CC] = fmaxf(y0, 0.0f);
            op_[(size_t)(2 * op + 1) * NN * CC] = fmaxf(y1, 0.0f);
        }
    }
}

// ---------------------------------------------------------------------------
extern "C" void kernel_launch(void* const* d_in, const int* in_sizes, int n_in,
                              void* d_out, int out_size)
{
    const float* x         = (const float*)d_in[0];
    const float* dists     = (const float*)d_in[1];
    const float* W         = (const float*)d_in[2];
    const float* bias      = (const float*)d_in[3];
    const int*   neighbors = (const int*)  d_in[4];
    float* out = (float*)d_out;

    k_prep<<<(NN + NT - 1) / NT, 256>>>(x, out);
    k_main<<<NN, 96>>>(dists, W, bias, neighbors, out);
}

// round 10
// speedup vs baseline: 3.1124x; 1.0935x over previous
#include <cuda_runtime.h>
#include <cuda_bf16.h>
#include <cuda_fp16.h>

#define NN     5000   // nodes
#define TIN    12     // input timesteps
#define TTOT   24     // output timesteps
#define BB     16     // batch
#define CC     4      // channels
#define KNB    16     // neighbors
#define NH     4      // heads
#define DIN    48     // T*H
#define DOUT   12     // extrapolated steps

// Transposed fp16 x scratch: xt[n][b][c][t] as __half (t fastest).
// 768 halves = 1536B per node = 96 x 16B chunks; chunk w holds half-positions
// 8w..8w+7, where pos = b*48 + c*12 + t.
__device__ __half g_xth[(size_t)NN * BB * CC * TIN];

typedef unsigned long long ull;

__device__ __forceinline__ ull pk2(float lo, float hi) {
    ull r;
    asm("mov.b64 %0, {%1, %2};" : "=l"(r) : "f"(lo), "f"(hi));
    return r;
}
__device__ __forceinline__ void upk2(float& lo, float& hi, ull v) {
    asm("mov.b64 {%0, %1}, %2;" : "=f"(lo), "=f"(hi) : "l"(v));
}
__device__ __forceinline__ void fma2(ull& d, ull a, ull b, ull c) {
    asm("fma.rn.f32x2 %0, %1, %2, %3;" : "=l"(d) : "l"(a), "l"(b), "l"(c));
}

// ---------------------------------------------------------------------------
// Kernel A (fused): read x (B,T,N,C) once;
//   (1) copy into out[:, 0:12] (coalesced, exact fp32),
//   (2) transpose+convert into g_xth[n][b][c][t] via smem (coalesced writes).
// ---------------------------------------------------------------------------
#define NT 8
#define SROW 772   // 768 floats per node + 4 pad (keeps 16B alignment)

__global__ __launch_bounds__(256) void k_prep(const float* __restrict__ x,
                                              float* __restrict__ out) {
    __shared__ __align__(16) float s[NT][SROW];

    const int tid = threadIdx.x;
    const int n0  = blockIdx.x * NT;
    const int nn  = tid & (NT - 1);
    const int mb  = tid >> 3;            // 0..31
    const int n   = n0 + nn;
    const bool valid = (n < NN);

    const float4* __restrict__ x4 = (const float4*)x;
    float4* __restrict__ out4 = (float4*)out;

    #pragma unroll
    for (int i = 0; i < 6; i++) {
        int m = mb + (i << 5);           // 0..191, m = b*12 + t
        if (valid) {
            float4 v = x4[(size_t)m * NN + n];
            int b = m / TIN, t = m % TIN;
            out4[((size_t)b * TTOT + t) * NN + n] = v;   // exact copy half
            float* sp = &s[nn][b * 48 + t];              // [b][c][t] layout
            sp[0]  = v.x;
            sp[12] = v.y;
            sp[24] = v.z;
            sp[36] = v.w;
        }
    }
    __syncthreads();

    // Phase 2: 96 16B-chunks per node, 8 nodes -> 768 stores, 3 iters.
    uint4* __restrict__ xth4 = (uint4*)g_xth;
    union H2U { __half2 h; unsigned u; };
    #pragma unroll
    for (int i = 0; i < 3; i++) {
        int g   = tid + (i << 8);        // 0..767
        int nn2 = g / 96;
        int w   = g - nn2 * 96;
        int n2  = n0 + nn2;
        if (n2 < NN) {
            const float4* sp = (const float4*)&s[nn2][w << 3];
            float4 a = sp[0], b = sp[1];
            H2U h0, h1, h2, h3;
            h0.h = __floats2half2_rn(a.x, a.y);
            h1.h = __floats2half2_rn(a.z, a.w);
            h2.h = __floats2half2_rn(b.x, b.y);
            h3.h = __floats2half2_rn(b.z, b.w);
            uint4 o;
            o.x = h0.u; o.y = h1.u; o.z = h2.u; o.w = h3.u;
            xth4[(size_t)n2 * 96 + w] = o;
        }
    }
}

// ---------------------------------------------------------------------------
// Kernel B: block per node, 96 threads.
// Phase A: thread owns the single 16B chunk tid of the 1536B fp16 node row ->
//   ONE LDG.128 per thread per k (warp = 512B contiguous), depth-3 pipeline.
//   cvt half2->float2, accumulate fp32 in f32x2: acc[4 pair][4 head].
// Stage fp32 agg via smem sagg[h][pos] (coalesced STS.128), then
// Phase B: threads 0..63 = (b,c) run the 48x12 linear with warp-uniform
//   broadcast sW reads, ReLU, store. (Identical to the proven R7 epilogue.)
// ---------------------------------------------------------------------------
__global__ __launch_bounds__(96, 10) void k_main(
    const float* __restrict__ dists,
    const float* __restrict__ W,
    const float* __restrict__ bias,
    const int*   __restrict__ neighbors,
    float* __restrict__ out)
{
    __shared__ ull   swp[KNB][NH];                 // packed (w,w) per (k,h)
    __shared__ int   snb[KNB];
    __shared__ __align__(16) float sW[DIN * DOUT];
    __shared__ float sb[DOUT];
    __shared__ __align__(16) float sagg[NH][192 * 4];   // [h][pos] as float4

    const int n   = blockIdx.x;
    const int tid = threadIdx.x;

    if (tid < KNB) {
        float d  = dists[n * KNB + tid];
        float e  = __expf(-d * d * (1.0f / 144.0f));   // sigma^2 = 36, H = 4
        float e2 = e * e;
        swp[tid][0] = pk2(e, e);
        swp[tid][1] = pk2(e2, e2);
        swp[tid][2] = pk2(e2 * e, e2 * e);
        swp[tid][3] = pk2(e2 * e2, e2 * e2);
        snb[tid]    = neighbors[n * KNB + tid];
    }
    #pragma unroll
    for (int i = tid; i < DIN * DOUT; i += 96) sW[i] = W[i];
    if (tid < DOUT) sb[tid] = bias[tid];
    __syncthreads();

    union F4U { float4 f; ull u[2]; };

    ull acc[4][NH];
    #pragma unroll
    for (int u = 0; u < 4; u++)
        #pragma unroll
        for (int h = 0; h < NH; h++) acc[u][h] = 0ull;

    const uint4* __restrict__ xp = ((const uint4*)g_xth) + tid;

    // Depth-3 software pipeline: 3 independent 16B loads in flight.
    uint4 buf[3];
    buf[0] = xp[(size_t)snb[0] * 96];
    buf[1] = xp[(size_t)snb[1] * 96];
    buf[2] = xp[(size_t)snb[2] * 96];

    #pragma unroll
    for (int k = 0; k < KNB; k++) {
        uint4 raw = buf[k % 3];
        if (k + 3 < KNB) buf[k % 3] = xp[(size_t)snb[k + 3] * 96];

        const __half2* hp = (const __half2*)&raw;
        ull xv[4];
        #pragma unroll
        for (int u = 0; u < 4; u++) {
            float2 f = __half22float2(hp[u]);
            xv[u] = pk2(f.x, f.y);
        }
        #pragma unroll
        for (int h = 0; h < NH; h++) {
            ull w = swp[k][h];
            fma2(acc[0][h], xv[0], w, acc[0][h]);
            fma2(acc[1][h], xv[1], w, acc[1][h]);
            fma2(acc[2][h], xv[2], w, acc[2][h]);
            fma2(acc[3][h], xv[3], w, acc[3][h]);
        }
    }

    // Stage aggregated values: chunk tid -> float positions 8*tid..8*tid+7
    float4* __restrict__ sagg4 = (float4*)sagg;
    #pragma unroll
    for (int h = 0; h < NH; h++) {
        F4U o0, o1;
        o0.u[0] = acc[0][h]; o0.u[1] = acc[1][h];
        o1.u[0] = acc[2][h]; o1.u[1] = acc[3][h];
        sagg4[h * 192 + 2 * tid]     = o0.f;
        sagg4[h * 192 + 2 * tid + 1] = o1.f;
    }
    __syncthreads();

    if (tid < 64) {
        // (b,c) = tid; its float4 chunks are at index 3*tid + tq (pos = 12*tid)
        ull y2[6];
        #pragma unroll
        for (int op = 0; op < 6; op++) y2[op] = pk2(sb[2 * op], sb[2 * op + 1]);

        #pragma unroll
        for (int tq = 0; tq < 3; tq++) {
            #pragma unroll
            for (int h = 0; h < NH; h++) {
                F4U f;
                f.f = sagg4[h * 192 + 3 * tid + tq];
                float fe[4] = { f.f.x, f.f.y, f.f.z, f.f.w };
                #pragma unroll
                for (int e = 0; e < 4; e++) {
                    int t = 4 * tq + e;
                    ull s = pk2(fe[e], fe[e]);
                    const ull* __restrict__ wr =
                        (const ull*)&sW[(t * NH + h) * DOUT];
                    #pragma unroll
                    for (int op = 0; op < 6; op++)
                        fma2(y2[op], s, wr[op], y2[op]);
                }
            }
        }

        const int b = tid >> 2;
        const int c = tid & 3;
        float* __restrict__ op_ =
            out + (((size_t)b * TTOT + TIN) * NN + n) * CC + c;
        #pragma unroll
        for (int op = 0; op < 6; op++) {
            float y0, y1;
            upk2(y0, y1, y2[op]);
            op_[(size_t)(2 * op)     * NN * CC] = fmaxf(y0, 0.0f);
            op_[(size_t)(2 * op + 1) * NN * CC] = fmaxf(y1, 0.0f);
        }
    }
}

// ---------------------------------------------------------------------------
extern "C" void kernel_launch(void* const* d_in, const int* in_sizes, int n_in,
                              void* d_out, int out_size)
{
    const float* x         = (const float*)d_in[0];
    const float* dists     = (const float*)d_in[1];
    const float* W         = (const float*)d_in[2];
    const float* bias      = (const float*)d_in[3];
    const int*   neighbors = (const int*)  d_in[4];
    float* out = (float*)d_out;

    k_prep<<<(NN + NT - 1) / NT, 256>>>(x, out);
    k_main<<<NN, 96>>>(dists, W, bias, neighbors, out);
}